// round 4
// baseline (speedup 1.0000x reference)
#include <cuda_runtime.h>

#define BB 16
#define PP 16
#define CC 1024
#define DD 128

__device__ float g_partial[BB*PP*4];   // per-block exp-sum partials (1024)

// ---------------------------------------------------------------------------
// K1: out[b,p,c] = exp(cand . w_c) for valid candidates, 0 for masked.
// (Row-constant score terms cancel in softmax; max-subtraction unnecessary
//  since |score| <~ 1.) Also emits one deterministic partial sum per block.
// 1024 blocks x 256 threads; warp owns 32 candidates, 8 loads in flight.
// ---------------------------------------------------------------------------
__global__ void __launch_bounds__(256) k_scores_exp(
    const float* __restrict__ cand_emb,
    const int*   __restrict__ cand_len,
    const float* __restrict__ score_w,
    float* __restrict__ out)
{
    __shared__ float sred[8];
    int bp = blockIdx.x >> 2, chunk = blockIdx.x & 3;
    int t = threadIdx.x, wid = t >> 5, lane = t & 31;

    float4 w4 = ((const float4*)(score_w + 3*DD))[lane];
    int clen = cand_len[bp];
    const float4* __restrict__ ce =
        (const float4*)cand_emb + (size_t)bp * (CC*DD/4);
    float* __restrict__ orow = out + (size_t)bp * CC;

    int c0 = chunk*256 + wid*32;
    int nv = clen - c0; nv = nv < 0 ? 0 : (nv > 32 ? 32 : nv);

    float wsum = 0.f;   // meaningful on lane 0
    int j = 0;
    // 8-wide batches: 8 independent LDG.128 in flight before the reduce chain
    for (; j + 8 <= nv; j += 8) {
        int c = c0 + j;
        float4 e0 = ce[(size_t)(c+0)*32 + lane];
        float4 e1 = ce[(size_t)(c+1)*32 + lane];
        float4 e2 = ce[(size_t)(c+2)*32 + lane];
        float4 e3 = ce[(size_t)(c+3)*32 + lane];
        float4 e4 = ce[(size_t)(c+4)*32 + lane];
        float4 e5 = ce[(size_t)(c+5)*32 + lane];
        float4 e6 = ce[(size_t)(c+6)*32 + lane];
        float4 e7 = ce[(size_t)(c+7)*32 + lane];
        float s0 = e0.x*w4.x + e0.y*w4.y + e0.z*w4.z + e0.w*w4.w;
        float s1 = e1.x*w4.x + e1.y*w4.y + e1.z*w4.z + e1.w*w4.w;
        float s2 = e2.x*w4.x + e2.y*w4.y + e2.z*w4.z + e2.w*w4.w;
        float s3 = e3.x*w4.x + e3.y*w4.y + e3.z*w4.z + e3.w*w4.w;
        float s4 = e4.x*w4.x + e4.y*w4.y + e4.z*w4.z + e4.w*w4.w;
        float s5 = e5.x*w4.x + e5.y*w4.y + e5.z*w4.z + e5.w*w4.w;
        float s6 = e6.x*w4.x + e6.y*w4.y + e6.z*w4.z + e6.w*w4.w;
        float s7 = e7.x*w4.x + e7.y*w4.y + e7.z*w4.z + e7.w*w4.w;
        #pragma unroll
        for (int o = 16; o > 0; o >>= 1) {
            s0 += __shfl_xor_sync(0xffffffffu, s0, o);
            s1 += __shfl_xor_sync(0xffffffffu, s1, o);
            s2 += __shfl_xor_sync(0xffffffffu, s2, o);
            s3 += __shfl_xor_sync(0xffffffffu, s3, o);
            s4 += __shfl_xor_sync(0xffffffffu, s4, o);
            s5 += __shfl_xor_sync(0xffffffffu, s5, o);
            s6 += __shfl_xor_sync(0xffffffffu, s6, o);
            s7 += __shfl_xor_sync(0xffffffffu, s7, o);
        }
        if (lane == 0) {
            float x0 = __expf(s0), x1 = __expf(s1), x2 = __expf(s2), x3 = __expf(s3);
            float x4 = __expf(s4), x5 = __expf(s5), x6 = __expf(s6), x7 = __expf(s7);
            *(float4*)(orow + c)     = make_float4(x0, x1, x2, x3);
            *(float4*)(orow + c + 4) = make_float4(x4, x5, x6, x7);
            wsum += ((x0 + x1) + (x2 + x3)) + ((x4 + x5) + (x6 + x7));
        }
    }
    // scalar tail
    for (; j < nv; j++) {
        int c = c0 + j;
        float4 e = ce[(size_t)c*32 + lane];
        float s = e.x*w4.x + e.y*w4.y + e.z*w4.z + e.w*w4.w;
        #pragma unroll
        for (int o = 16; o > 0; o >>= 1) s += __shfl_xor_sync(0xffffffffu, s, o);
        if (lane == 0) {
            float x = __expf(s);
            orow[c] = x;
            wsum += x;
        }
    }
    // masked tail: coalesced zero fill
    int cm = c0 + nv + lane;
    if (cm < c0 + 32) orow[cm] = 0.0f;

    // deterministic block partial: lane0 per warp -> thread 0 fixed-order sum
    if (lane == 0) sred[wid] = wsum;
    __syncthreads();
    if (t == 0) {
        float s = 0.f;
        #pragma unroll
        for (int w = 0; w < 8; w++) s += sred[w];
        g_partial[blockIdx.x] = s;
    }
}

// ---------------------------------------------------------------------------
// K2: per-batch normalize. 256 blocks (16 per batch) x 256 threads.
// Each block deterministically sums its batch's 64 partials, then scales
// its 1024-float slice (one float4 per thread). Full-grid 4MB sweep.
// ---------------------------------------------------------------------------
__global__ void __launch_bounds__(256) k_norm(float* __restrict__ out)
{
    __shared__ float inv_sh;
    int b = blockIdx.x >> 4, blk = blockIdx.x & 15;
    int t = threadIdx.x;

    if (t < 32) {
        float v = g_partial[b*64 + t] + g_partial[b*64 + 32 + t];
        #pragma unroll
        for (int o = 16; o > 0; o >>= 1)
            v += __shfl_xor_sync(0xffffffffu, v, o);
        if (t == 0) inv_sh = 1.0f / v;
    }
    __syncthreads();
    float inv = inv_sh;

    float4* row4 = (float4*)(out + (size_t)b * 16384);
    int idx = blk*256 + t;          // 4096 float4 per batch
    float4 v = row4[idx];
    v.x *= inv; v.y *= inv; v.z *= inv; v.w *= inv;
    row4[idx] = v;
}

// ---------------------------------------------------------------------------
extern "C" void kernel_launch(void* const* d_in, const int* in_sizes, int n_in,
                              void* d_out, int out_size)
{
    const float* cand_emb = (const float*)d_in[3];
    const int*   cand_len = (const int*)  d_in[4];
    const float* score_w  = (const float*)d_in[19];
    float* out = (float*)d_out;

    k_scores_exp<<<BB*PP*4, 256>>>(cand_emb, cand_len, score_w, out);
    k_norm<<<BB*PP, 256>>>(out);
}

// round 5
// speedup vs baseline: 1.3013x; 1.3013x over previous
#include <cuda_runtime.h>

#define BB 16
#define PP 16
#define CC 1024
#define DD 128

__device__ float g_partial[BB*64];   // per-block exp-sum partials (64 per batch)
__device__ int   g_count[BB];        // arrival counters (zero-init; self-reset)

// ---------------------------------------------------------------------------
// Single fused kernel:
//  Phase 1 (all 1024 blocks): out[b,p,c] = exp(cand . w_c) (valid) / 0 (masked),
//    exactly the R2-proven 4-wide warp-dot structure. Block partial sum ->
//    g_partial, arrival -> g_count[b].
//  Phase 2 (last-arriving block per batch only): fixed-order sum of the 64
//    partials, normalize the batch's 16384 exps (64KB, L2-hot), reset counter.
//  Row-constant score terms cancel in softmax; |score| <~ 1 so no max needed;
//  masked entries are exactly 0 in both reference and kernel.
// ---------------------------------------------------------------------------
__global__ void __launch_bounds__(256) k_fused(
    const float* __restrict__ cand_emb,
    const int*   __restrict__ cand_len,
    const float* __restrict__ score_w,
    float* __restrict__ out)
{
    __shared__ float sred[8];
    __shared__ int   s_last;
    __shared__ float s_inv;

    int bp = blockIdx.x >> 2, chunk = blockIdx.x & 3;
    int b = bp >> 4;
    int t = threadIdx.x, wid = t >> 5, lane = t & 31;

    float4 w4 = ((const float4*)(score_w + 3*DD))[lane];
    int clen = cand_len[bp];
    const float4* __restrict__ ce =
        (const float4*)cand_emb + (size_t)bp * (CC*DD/4);
    float* __restrict__ orow = out + (size_t)bp * CC;

    int c0 = chunk*256 + wid*32;
    int nv = clen - c0; nv = nv < 0 ? 0 : (nv > 32 ? 32 : nv);

    float wsum = 0.f;   // meaningful on lane 0
    int j = 0;
    // 4-wide batches: 4 independent LDG.128 in flight before the reduce chain
    for (; j + 4 <= nv; j += 4) {
        int c = c0 + j;
        float4 e0 = ce[(size_t)(c+0)*32 + lane];
        float4 e1 = ce[(size_t)(c+1)*32 + lane];
        float4 e2 = ce[(size_t)(c+2)*32 + lane];
        float4 e3 = ce[(size_t)(c+3)*32 + lane];
        float s0 = e0.x*w4.x + e0.y*w4.y + e0.z*w4.z + e0.w*w4.w;
        float s1 = e1.x*w4.x + e1.y*w4.y + e1.z*w4.z + e1.w*w4.w;
        float s2 = e2.x*w4.x + e2.y*w4.y + e2.z*w4.z + e2.w*w4.w;
        float s3 = e3.x*w4.x + e3.y*w4.y + e3.z*w4.z + e3.w*w4.w;
        #pragma unroll
        for (int o = 16; o > 0; o >>= 1) {
            s0 += __shfl_xor_sync(0xffffffffu, s0, o);
            s1 += __shfl_xor_sync(0xffffffffu, s1, o);
            s2 += __shfl_xor_sync(0xffffffffu, s2, o);
            s3 += __shfl_xor_sync(0xffffffffu, s3, o);
        }
        if (lane == 0) {
            float x0 = __expf(s0), x1 = __expf(s1);
            float x2 = __expf(s2), x3 = __expf(s3);
            *(float4*)(orow + c) = make_float4(x0, x1, x2, x3);
            wsum += (x0 + x1) + (x2 + x3);
        }
    }
    // scalar tail
    for (; j < nv; j++) {
        int c = c0 + j;
        float4 e = ce[(size_t)c*32 + lane];
        float s = e.x*w4.x + e.y*w4.y + e.z*w4.z + e.w*w4.w;
        #pragma unroll
        for (int o = 16; o > 0; o >>= 1) s += __shfl_xor_sync(0xffffffffu, s, o);
        if (lane == 0) {
            float x = __expf(s);
            orow[c] = x;
            wsum += x;
        }
    }
    // masked tail: coalesced zero fill
    int cm = c0 + nv + lane;
    if (cm < c0 + 32) orow[cm] = 0.0f;

    // --- block partial + arrival (deterministic fixed-order sums) ---
    if (lane == 0) sred[wid] = wsum;
    __syncthreads();
    if (t == 0) {
        float s = 0.f;
        #pragma unroll
        for (int w = 0; w < 8; w++) s += sred[w];
        int slot = ((bp & 15) << 2) | chunk;       // 0..63 within batch
        g_partial[b*64 + slot] = s;
        __threadfence();                            // release partial
        int old = atomicAdd(&g_count[b], 1);
        s_last = (old == 63) ? 1 : 0;
    }
    __syncthreads();
    if (!s_last) return;

    // ================= Phase 2: last block of batch b =================
    if (t == 0) {
        g_count[b] = 0;                 // self-reset for graph replay
        __threadfence();                // acquire: order partial reads after atomic
    }
    __syncthreads();

    // fixed-tree sum of 64 partials (warp 0), broadcast via shared
    if (wid == 0) {
        float v = g_partial[b*64 + lane] + g_partial[b*64 + 32 + lane];
        #pragma unroll
        for (int o = 16; o > 0; o >>= 1)
            v += __shfl_xor_sync(0xffffffffu, v, o);
        if (lane == 0) s_inv = 1.0f / v;
    }
    __syncthreads();
    float inv = s_inv;

    // normalize the whole batch row: 16384 floats = 4096 float4 (L2-hot)
    float4* __restrict__ row4 = (float4*)(out + (size_t)b * 16384);
    #pragma unroll 4
    for (int i = t; i < 4096; i += 256) {
        float4 v = row4[i];
        v.x *= inv; v.y *= inv; v.z *= inv; v.w *= inv;
        row4[i] = v;
    }
}

// ---------------------------------------------------------------------------
extern "C" void kernel_launch(void* const* d_in, const int* in_sizes, int n_in,
                              void* d_out, int out_size)
{
    const float* cand_emb = (const float*)d_in[3];
    const int*   cand_len = (const int*)  d_in[4];
    const float* score_w  = (const float*)d_in[19];
    float* out = (float*)d_out;

    k_fused<<<BB*PP*4, 256>>>(cand_emb, cand_len, score_w, out);
}